// round 15
// baseline (speedup 1.0000x reference)
#include <cuda_runtime.h>

#define B_TOT   8192
#define T_STEPS 100
#define IN_DIM  32
#define H_DIM   32
#define HID     20
#define HGRP    10
#define NRK     8

// group-1 weight rows are skewed +4 floats (16B) to land on disjoint banks
#define GSKEW   4
#define GSTRIDE (HGRP * 32 + GSKEW)   // 324 floats per group block

typedef unsigned long long u64;

// ---- packed f32x2 helpers (sm_103a) ----
__device__ __forceinline__ u64 pk(float lo, float hi) {
    u64 d; asm("mov.b64 %0, {%1, %2};" : "=l"(d) : "f"(lo), "f"(hi)); return d;
}
__device__ __forceinline__ void upk(u64 d, float& lo, float& hi) {
    asm("mov.b64 {%0, %1}, %2;" : "=f"(lo), "=f"(hi) : "l"(d));
}
__device__ __forceinline__ u64 pfma(u64 a, u64 b, u64 c) {
    u64 d; asm("fma.rn.f32x2 %0, %1, %2, %3;" : "=l"(d) : "l"(a), "l"(b), "l"(c)); return d;
}
__device__ __forceinline__ u64 pmul(u64 a, u64 b) {
    u64 d; asm("mul.rn.f32x2 %0, %1, %2;" : "=l"(d) : "l"(a), "l"(b)); return d;
}
__device__ __forceinline__ u64 padd(u64 a, u64 b) {
    u64 d; asm("add.rn.f32x2 %0, %1, %2;" : "=l"(d) : "l"(a), "l"(b)); return d;
}

// 4-lane quad sum (xor 1,2): result broadcast within each aligned quad.
__device__ __forceinline__ float redux4(float v) {
    v += __shfl_xor_sync(0xffffffffu, v, 1);
    v += __shfl_xor_sync(0xffffffffu, v, 2);
    return v;
}

// exact-ish tanh: 1 - 2/(exp(2x)+1); ~1e-7 abs err.
__device__ __forceinline__ float ftanh(float x) {
    float e = __expf(2.0f * x);
    return 1.0f - __fdividef(2.0f, e + 1.0f);
}
// HW tanh (~5e-4 worst abs err) — only inside the ODE func (result scaled ~1e-4).
__device__ __forceinline__ float tanha(float x) {
    float y; asm("tanh.approx.f32 %0, %1;" : "=f"(y) : "f"(x)); return y;
}

// dot of 8 owned lanes (4 packed pairs) with a 32B weight slice, partial only.
__device__ __forceinline__ float dot8(const u64 zp[4], const float* wrow) {
    const ulonglong2* p = reinterpret_cast<const ulonglong2*>(wrow);
    ulonglong2 wa = p[0], wb = p[1];
    u64 s2 = pmul(zp[0], wa.x);
    s2 = pfma(zp[1], wa.y, s2);
    s2 = pfma(zp[2], wb.x, s2);
    s2 = pfma(zp[3], wb.y, s2);
    float lo, hi; upk(s2, lo, hi);
    return lo + hi;
}

// One ODE-func eval. 8 threads/element = 2 groups x 4 threads.
// Group owns 10 hidden rows (group-1 rows bank-skewed +16B); z replicated
// across groups, split 4-ways within group. Layer-2 partials summed via xor-4.
__device__ __forceinline__ void feval(const u64 zp[4], const float c[HGRP],
                                      const float* sW1g, const float* sW2g,
                                      const u64 bf[4], int base8, u64 up[4])
{
    u64 a0 = bf[0], a1 = bf[1], a2 = bf[2], a3 = bf[3];
#pragma unroll
    for (int jj = 0; jj < HGRP; ++jj) {
        float r = redux4(dot8(zp, sW1g + jj * 32 + base8)) + c[jj];
        r = fmaxf(r, 0.0f);
        u64 rr = pk(r, r);
        const ulonglong2* w2 = reinterpret_cast<const ulonglong2*>(sW2g + jj * 32 + base8);
        ulonglong2 va = w2[0], vb = w2[1];
        a0 = pfma(rr, va.x, a0);
        a1 = pfma(rr, va.y, a1);
        a2 = pfma(rr, vb.x, a2);
        a3 = pfma(rr, vb.y, a3);
    }
    // cross-group sum (xor 4) + tanh
    u64 acc[4] = {a0, a1, a2, a3};
#pragma unroll
    for (int i = 0; i < 4; ++i) {
        float lo, hi; upk(acc[i], lo, hi);
        lo += __shfl_xor_sync(0xffffffffu, lo, 4);
        hi += __shfl_xor_sync(0xffffffffu, hi, 4);
        up[i] = pk(tanha(lo), tanha(hi));
    }
}

__global__ __launch_bounds__(64, 5)
void latode_kernel(const float* __restrict__ dt,  const float* __restrict__ x,
                   const float* __restrict__ We1, const float* __restrict__ be1,
                   const float* __restrict__ We2, const float* __restrict__ be2,
                   const float* __restrict__ Wf1, const float* __restrict__ bf1,
                   const float* __restrict__ Wf2, const float* __restrict__ bf2,
                   const float* __restrict__ Wm1, const float* __restrict__ bm1,
                   const float* __restrict__ Wm2, const float* __restrict__ bm2,
                   float* __restrict__ out)
{
    // group-skewed layouts: row j lives at j*32 + (j>=10 ? GSKEW : 0)
    __shared__ __align__(16) float sW1z[2 * GSTRIDE];   // [j][i]  z-part of Wf1, transposed
    __shared__ __align__(16) float sW1x[2 * GSTRIDE];   // [j][i]  x-part of Wf1, transposed
    __shared__ __align__(16) float sW2 [2 * GSTRIDE];   // [j][o]  Wf2 natural
    __shared__ __align__(16) float sWe1T[10 * 32];      // [m][i]
    __shared__ __align__(16) float sWe2 [10 * 32];      // [m][o]
    __shared__ __align__(16) float sWm1T[10 * 32];      // [m][i]
    __shared__ float sbf1[HID], sbf2[32], sbe1[10], sbe2[32], sbm1[10], sWm2v[10], sbm2;

    const int tid = threadIdx.x;
    for (int idx = tid; idx < HID * 32; idx += blockDim.x) {
        int j = idx >> 5, i = idx & 31;
        int a = j * 32 + i + ((j >= HGRP) ? GSKEW : 0);
        sW1z[a] = Wf1[i * HID + j];
        sW1x[a] = Wf1[(32 + i) * HID + j];
        sW2[a]  = Wf2[j * 32 + i];
    }
    for (int idx = tid; idx < 10 * 32; idx += blockDim.x) {
        int m = idx >> 5, i = idx & 31;
        sWe1T[idx] = We1[i * 10 + m];
        sWe2[idx]  = We2[m * 32 + i];
        sWm1T[idx] = Wm1[i * 10 + m];
    }
    if (tid < HID) sbf1[tid] = bf1[tid];
    if (tid < 32)  { sbf2[tid] = bf2[tid]; sbe2[tid] = be2[tid]; }
    if (tid < 10)  { sbe1[tid] = be1[tid]; sbm1[tid] = bm1[tid]; sWm2v[tid] = Wm2[tid]; }
    if (tid == 0)  sbm2 = bm2[0];
    __syncthreads();

    const int gt    = blockIdx.x * blockDim.x + tid;
    const int b     = gt >> 3;          // element id
    const int g     = gt & 7;           // sub-thread within element
    const int grp   = g >> 2;           // row group: 0 -> rows 0..9, 1 -> rows 10..19
    const int base8 = (g & 3) * 8;      // owned z/output lane window [base8, base8+8)

    const float* sW1g  = sW1z + grp * GSTRIDE;
    const float* sW1xg = sW1x + grp * GSTRIDE;
    const float* sW2g  = sW2  + grp * GSTRIDE;
    const float* sbf1g = sbf1 + grp * HGRP;

    const float hs = 1.0f / NRK;

    // bf2 bias pairs: group 0 carries the bias, group 1 contributes zero
    u64 bfp[4];
#pragma unroll
    for (int i = 0; i < 4; ++i)
        bfp[i] = (grp == 0) ? pk(sbf2[base8 + 2*i], sbf2[base8 + 2*i + 1]) : 0ull;

    // ---- encoder: z0 = tanh(tanh(x0@We1+be1)@We2+be2) (group-redundant) ----
    u64 xp[4];
    {
        const float4* q = reinterpret_cast<const float4*>(x + (size_t)b * T_STEPS * IN_DIM + base8);
        float4 qa = q[0], qb = q[1];
        xp[0] = pk(qa.x, qa.y); xp[1] = pk(qa.z, qa.w);
        xp[2] = pk(qb.x, qb.y); xp[3] = pk(qb.z, qb.w);
    }
    float h10[10];
#pragma unroll
    for (int m = 0; m < 10; ++m)
        h10[m] = ftanh(redux4(dot8(xp, sWe1T + m * 32 + base8)) + sbe1[m]);
    u64 zp[4];
#pragma unroll
    for (int p = 0; p < 4; ++p) {
        float s0 = sbe2[base8 + 2*p], s1 = sbe2[base8 + 2*p + 1];
#pragma unroll
        for (int m = 0; m < 10; ++m) {
            const float* w = sWe2 + m * 32 + base8 + 2*p;
            s0 += h10[m] * w[0]; s1 += h10[m] * w[1];
        }
        zp[p] = pk(ftanh(s0), ftanh(s1));
    }

    // ---- time loop ----
#pragma unroll 1
    for (int t = 0; t < T_STEPS; ++t) {
        {
            const float4* q = reinterpret_cast<const float4*>(
                x + ((size_t)b * T_STEPS + t) * IN_DIM + base8);
            float4 qa = q[0], qb = q[1];
            xp[0] = pk(qa.x, qa.y); xp[1] = pk(qa.z, qa.w);
            xp[2] = pk(qb.x, qb.y); xp[3] = pk(qb.z, qb.w);
        }
        const float2 dpair = *reinterpret_cast<const float2*>(dt + ((size_t)b * T_STEPS + t) * 2);
        const float sc = (dpair.y - dpair.x) * 0.01f;   // d * DT_SCALER
        const float ah = 0.5f * hs * sc;
        const float af = hs * sc;
        const float a6 = (hs / 6.0f) * sc;
        const u64 ahp = pk(ah, ah);
        const u64 afp = pk(af, af);
        const u64 a6p = pk(a6, a6);
        const u64 twp = pk(2.0f, 2.0f);

        // c[jj] = (x_i @ W1x)[group rows] + bf1 — constant across this step's 32 f-evals
        float c[HGRP];
#pragma unroll
        for (int jj = 0; jj < HGRP; ++jj)
            c[jj] = redux4(dot8(xp, sW1xg + jj * 32 + base8)) + sbf1g[jj];

#pragma unroll 1
        for (int rk = 0; rk < NRK; ++rk) {
            u64 up[4], sup[4], zcp[4];
            feval(zp, c, sW1g, sW2g, bfp, base8, up);     // k1
#pragma unroll
            for (int p = 0; p < 4; ++p) { sup[p] = up[p]; zcp[p] = pfma(up[p], ahp, zp[p]); }
            feval(zcp, c, sW1g, sW2g, bfp, base8, up);    // k2
#pragma unroll
            for (int p = 0; p < 4; ++p) { sup[p] = pfma(up[p], twp, sup[p]); zcp[p] = pfma(up[p], ahp, zp[p]); }
            feval(zcp, c, sW1g, sW2g, bfp, base8, up);    // k3
#pragma unroll
            for (int p = 0; p < 4; ++p) { sup[p] = pfma(up[p], twp, sup[p]); zcp[p] = pfma(up[p], afp, zp[p]); }
            feval(zcp, c, sW1g, sW2g, bfp, base8, up);    // k4
#pragma unroll
            for (int p = 0; p < 4; ++p) zp[p] = pfma(padd(sup[p], up[p]), a6p, zp[p]);
        }

        // mu = tanh(z@Wm1+bm1)@Wm2 + bm2 (group-redundant; exact tanh)
        float mu = sbm2;
#pragma unroll
        for (int m = 0; m < 10; ++m) {
            float hm = ftanh(redux4(dot8(zp, sWm1T + m * 32 + base8)) + sbm1[m]);
            mu += hm * sWm2v[m];
        }
        if (g == 0) out[(size_t)b * T_STEPS + t] = mu;
    }
}

extern "C" void kernel_launch(void* const* d_in, const int* in_sizes, int n_in,
                              void* d_out, int out_size)
{
    const float* dt  = (const float*)d_in[0];
    const float* x   = (const float*)d_in[1];
    const float* We1 = (const float*)d_in[2];
    const float* be1 = (const float*)d_in[3];
    const float* We2 = (const float*)d_in[4];
    const float* be2 = (const float*)d_in[5];
    const float* Wf1 = (const float*)d_in[6];
    const float* bf1 = (const float*)d_in[7];
    const float* Wf2 = (const float*)d_in[8];
    const float* bf2 = (const float*)d_in[9];
    const float* Wm1 = (const float*)d_in[10];
    const float* bm1 = (const float*)d_in[11];
    const float* Wm2 = (const float*)d_in[12];
    const float* bm2 = (const float*)d_in[13];
    float* out = (float*)d_out;

    // 8 threads per batch element: 65536 threads, 1024 CTAs of 64
    dim3 block(64);
    dim3 grid((B_TOT * 8) / 64);
    latode_kernel<<<grid, block>>>(dt, x, We1, be1, We2, be2,
                                   Wf1, bf1, Wf2, bf2, Wm1, bm1, Wm2, bm2, out);
}

// round 16
// speedup vs baseline: 2.2752x; 2.2752x over previous
#include <cuda_runtime.h>

#define B_TOT   8192
#define T_STEPS 100
#define IN_DIM  32
#define H_DIM   32
#define HID     20
#define HGRP    10
#define NRK     8

// group-1 weight rows are skewed +4 floats (16B) to land on disjoint banks
#define GSKEW   4
#define GSTRIDE (HGRP * 32 + GSKEW)   // 324 floats per group block

typedef unsigned long long u64;

// ---- packed f32x2 helpers (sm_103a) ----
__device__ __forceinline__ u64 pk(float lo, float hi) {
    u64 d; asm("mov.b64 %0, {%1, %2};" : "=l"(d) : "f"(lo), "f"(hi)); return d;
}
__device__ __forceinline__ void upk(u64 d, float& lo, float& hi) {
    asm("mov.b64 {%0, %1}, %2;" : "=f"(lo), "=f"(hi) : "l"(d));
}
__device__ __forceinline__ u64 pfma(u64 a, u64 b, u64 c) {
    u64 d; asm("fma.rn.f32x2 %0, %1, %2, %3;" : "=l"(d) : "l"(a), "l"(b), "l"(c)); return d;
}
__device__ __forceinline__ u64 pmul(u64 a, u64 b) {
    u64 d; asm("mul.rn.f32x2 %0, %1, %2;" : "=l"(d) : "l"(a), "l"(b)); return d;
}
__device__ __forceinline__ u64 padd(u64 a, u64 b) {
    u64 d; asm("add.rn.f32x2 %0, %1, %2;" : "=l"(d) : "l"(a), "l"(b)); return d;
}

// 4-lane quad sum (xor 1,2): result broadcast within each aligned quad.
__device__ __forceinline__ float redux4(float v) {
    v += __shfl_xor_sync(0xffffffffu, v, 1);
    v += __shfl_xor_sync(0xffffffffu, v, 2);
    return v;
}

// exact-ish tanh: 1 - 2/(exp(2x)+1); ~1e-7 abs err.
__device__ __forceinline__ float ftanh(float x) {
    float e = __expf(2.0f * x);
    return 1.0f - __fdividef(2.0f, e + 1.0f);
}
// HW tanh (~5e-4 worst abs err) — only inside the ODE func (result scaled ~1e-4).
__device__ __forceinline__ float tanha(float x) {
    float y; asm("tanh.approx.f32 %0, %1;" : "=f"(y) : "f"(x)); return y;
}

// dot of 8 owned lanes (4 packed pairs) with a 32B smem weight slice.
__device__ __forceinline__ float dot8s(const u64 zp[4], const float* wrow) {
    const ulonglong2* p = reinterpret_cast<const ulonglong2*>(wrow);
    ulonglong2 wa = p[0], wb = p[1];
    u64 s2 = pmul(zp[0], wa.x);
    s2 = pfma(zp[1], wa.y, s2);
    s2 = pfma(zp[2], wb.x, s2);
    s2 = pfma(zp[3], wb.y, s2);
    float lo, hi; upk(s2, lo, hi);
    return lo + hi;
}

// One ODE-func eval, weights fully register-resident.
// 8 threads/element = 2 groups x 4 threads; group owns 10 hidden rows.
// up = tanh(relu(zc@W1z + c)@W2 + bf2) for the 8 owned output lanes.
__device__ __forceinline__ void feval(const u64 zp[4], const float c[HGRP],
                                      const u64 w1r[4 * HGRP], const u64 w2r[4 * HGRP],
                                      const u64 bf[4], u64 up[4])
{
    u64 a0 = bf[0], a1 = bf[1], a2 = bf[2], a3 = bf[3];
#pragma unroll
    for (int jj = 0; jj < HGRP; ++jj) {
        u64 s2 = pmul(zp[0], w1r[4*jj + 0]);
        s2 = pfma(zp[1], w1r[4*jj + 1], s2);
        s2 = pfma(zp[2], w1r[4*jj + 2], s2);
        s2 = pfma(zp[3], w1r[4*jj + 3], s2);
        float lo, hi; upk(s2, lo, hi);
        float r = redux4(lo + hi) + c[jj];
        r = fmaxf(r, 0.0f);
        u64 rr = pk(r, r);
        a0 = pfma(rr, w2r[4*jj + 0], a0);
        a1 = pfma(rr, w2r[4*jj + 1], a1);
        a2 = pfma(rr, w2r[4*jj + 2], a2);
        a3 = pfma(rr, w2r[4*jj + 3], a3);
    }
    // cross-group sum (xor 4) + tanh
    u64 acc[4] = {a0, a1, a2, a3};
#pragma unroll
    for (int i = 0; i < 4; ++i) {
        float lo, hi; upk(acc[i], lo, hi);
        lo += __shfl_xor_sync(0xffffffffu, lo, 4);
        hi += __shfl_xor_sync(0xffffffffu, hi, 4);
        up[i] = pk(tanha(lo), tanha(hi));
    }
}

__global__ __launch_bounds__(64)
void latode_kernel(const float* __restrict__ dt,  const float* __restrict__ x,
                   const float* __restrict__ We1, const float* __restrict__ be1,
                   const float* __restrict__ We2, const float* __restrict__ be2,
                   const float* __restrict__ Wf1, const float* __restrict__ bf1,
                   const float* __restrict__ Wf2, const float* __restrict__ bf2,
                   const float* __restrict__ Wm1, const float* __restrict__ bm1,
                   const float* __restrict__ Wm2, const float* __restrict__ bm2,
                   float* __restrict__ out)
{
    // group-skewed layouts: row j lives at j*32 + (j>=10 ? GSKEW : 0)
    __shared__ __align__(16) float sW1z[2 * GSTRIDE];   // [j][i]  z-part of Wf1, transposed
    __shared__ __align__(16) float sW1x[2 * GSTRIDE];   // [j][i]  x-part of Wf1, transposed
    __shared__ __align__(16) float sW2 [2 * GSTRIDE];   // [j][o]  Wf2 natural
    __shared__ __align__(16) float sWe1T[10 * 32];      // [m][i]
    __shared__ __align__(16) float sWe2 [10 * 32];      // [m][o]
    __shared__ __align__(16) float sWm1T[10 * 32];      // [m][i]
    __shared__ float sbf1[HID], sbf2[32], sbe1[10], sbe2[32], sbm1[10], sWm2v[10], sbm2;

    const int tid = threadIdx.x;
    for (int idx = tid; idx < HID * 32; idx += blockDim.x) {
        int j = idx >> 5, i = idx & 31;
        int a = j * 32 + i + ((j >= HGRP) ? GSKEW : 0);
        sW1z[a] = Wf1[i * HID + j];
        sW1x[a] = Wf1[(32 + i) * HID + j];
        sW2[a]  = Wf2[j * 32 + i];
    }
    for (int idx = tid; idx < 10 * 32; idx += blockDim.x) {
        int m = idx >> 5, i = idx & 31;
        sWe1T[idx] = We1[i * 10 + m];
        sWe2[idx]  = We2[m * 32 + i];
        sWm1T[idx] = Wm1[i * 10 + m];
    }
    if (tid < HID) sbf1[tid] = bf1[tid];
    if (tid < 32)  { sbf2[tid] = bf2[tid]; sbe2[tid] = be2[tid]; }
    if (tid < 10)  { sbe1[tid] = be1[tid]; sbm1[tid] = bm1[tid]; sWm2v[tid] = Wm2[tid]; }
    if (tid == 0)  sbm2 = bm2[0];
    __syncthreads();

    const int gt    = blockIdx.x * blockDim.x + tid;
    const int b     = gt >> 3;          // element id
    const int g     = gt & 7;           // sub-thread within element
    const int grp   = g >> 2;           // row group: 0 -> rows 0..9, 1 -> rows 10..19
    const int base8 = (g & 3) * 8;      // owned z/output lane window [base8, base8+8)

    const float* sW1xg = sW1x + grp * GSTRIDE;
    const float* sbf1g = sbf1 + grp * HGRP;

    // ---- hoist this thread's ODE-func weight slices into registers ----
    u64 w1r[4 * HGRP], w2r[4 * HGRP];
    {
        const float* sW1g = sW1z + grp * GSTRIDE;
        const float* sW2g = sW2  + grp * GSTRIDE;
#pragma unroll
        for (int jj = 0; jj < HGRP; ++jj) {
            const ulonglong2* p1 = reinterpret_cast<const ulonglong2*>(sW1g + jj * 32 + base8);
            ulonglong2 qa = p1[0], qb = p1[1];
            w1r[4*jj + 0] = qa.x; w1r[4*jj + 1] = qa.y;
            w1r[4*jj + 2] = qb.x; w1r[4*jj + 3] = qb.y;
            const ulonglong2* p2 = reinterpret_cast<const ulonglong2*>(sW2g + jj * 32 + base8);
            ulonglong2 ra = p2[0], rb = p2[1];
            w2r[4*jj + 0] = ra.x; w2r[4*jj + 1] = ra.y;
            w2r[4*jj + 2] = rb.x; w2r[4*jj + 3] = rb.y;
        }
    }

    const float hs = 1.0f / NRK;

    // bf2 bias pairs: group 0 carries the bias, group 1 contributes zero
    u64 bfp[4];
#pragma unroll
    for (int i = 0; i < 4; ++i)
        bfp[i] = (grp == 0) ? pk(sbf2[base8 + 2*i], sbf2[base8 + 2*i + 1]) : 0ull;

    // ---- encoder: z0 = tanh(tanh(x0@We1+be1)@We2+be2) (group-redundant) ----
    u64 xp[4];
    {
        const float4* q = reinterpret_cast<const float4*>(x + (size_t)b * T_STEPS * IN_DIM + base8);
        float4 qa = q[0], qb = q[1];
        xp[0] = pk(qa.x, qa.y); xp[1] = pk(qa.z, qa.w);
        xp[2] = pk(qb.x, qb.y); xp[3] = pk(qb.z, qb.w);
    }
    float h10[10];
#pragma unroll
    for (int m = 0; m < 10; ++m)
        h10[m] = ftanh(redux4(dot8s(xp, sWe1T + m * 32 + base8)) + sbe1[m]);
    u64 zp[4];
#pragma unroll
    for (int p = 0; p < 4; ++p) {
        float s0 = sbe2[base8 + 2*p], s1 = sbe2[base8 + 2*p + 1];
#pragma unroll
        for (int m = 0; m < 10; ++m) {
            const float* w = sWe2 + m * 32 + base8 + 2*p;
            s0 += h10[m] * w[0]; s1 += h10[m] * w[1];
        }
        zp[p] = pk(ftanh(s0), ftanh(s1));
    }

    // ---- time loop ----
#pragma unroll 1
    for (int t = 0; t < T_STEPS; ++t) {
        {
            const float4* q = reinterpret_cast<const float4*>(
                x + ((size_t)b * T_STEPS + t) * IN_DIM + base8);
            float4 qa = q[0], qb = q[1];
            xp[0] = pk(qa.x, qa.y); xp[1] = pk(qa.z, qa.w);
            xp[2] = pk(qb.x, qb.y); xp[3] = pk(qb.z, qb.w);
        }
        const float2 dpair = *reinterpret_cast<const float2*>(dt + ((size_t)b * T_STEPS + t) * 2);
        const float sc = (dpair.y - dpair.x) * 0.01f;   // d * DT_SCALER
        const float ah = 0.5f * hs * sc;
        const float af = hs * sc;
        const float a6 = (hs / 6.0f) * sc;
        const u64 ahp = pk(ah, ah);
        const u64 afp = pk(af, af);
        const u64 a6p = pk(a6, a6);
        const u64 twp = pk(2.0f, 2.0f);

        // c[jj] = (x_i @ W1x)[group rows] + bf1 — constant across this step's 32 f-evals
        float c[HGRP];
#pragma unroll
        for (int jj = 0; jj < HGRP; ++jj)
            c[jj] = redux4(dot8s(xp, sW1xg + jj * 32 + base8)) + sbf1g[jj];

#pragma unroll 1
        for (int rk = 0; rk < NRK; ++rk) {
            u64 up[4], sup[4], zcp[4];
            feval(zp, c, w1r, w2r, bfp, up);     // k1
#pragma unroll
            for (int p = 0; p < 4; ++p) { sup[p] = up[p]; zcp[p] = pfma(up[p], ahp, zp[p]); }
            feval(zcp, c, w1r, w2r, bfp, up);    // k2
#pragma unroll
            for (int p = 0; p < 4; ++p) { sup[p] = pfma(up[p], twp, sup[p]); zcp[p] = pfma(up[p], ahp, zp[p]); }
            feval(zcp, c, w1r, w2r, bfp, up);    // k3
#pragma unroll
            for (int p = 0; p < 4; ++p) { sup[p] = pfma(up[p], twp, sup[p]); zcp[p] = pfma(up[p], afp, zp[p]); }
            feval(zcp, c, w1r, w2r, bfp, up);    // k4
#pragma unroll
            for (int p = 0; p < 4; ++p) zp[p] = pfma(padd(sup[p], up[p]), a6p, zp[p]);
        }

        // mu = tanh(z@Wm1+bm1)@Wm2 + bm2 (group-redundant; exact tanh)
        float mu = sbm2;
#pragma unroll
        for (int m = 0; m < 10; ++m) {
            float hm = ftanh(redux4(dot8s(zp, sWm1T + m * 32 + base8)) + sbm1[m]);
            mu += hm * sWm2v[m];
        }
        if (g == 0) out[(size_t)b * T_STEPS + t] = mu;
    }
}

extern "C" void kernel_launch(void* const* d_in, const int* in_sizes, int n_in,
                              void* d_out, int out_size)
{
    const float* dt  = (const float*)d_in[0];
    const float* x   = (const float*)d_in[1];
    const float* We1 = (const float*)d_in[2];
    const float* be1 = (const float*)d_in[3];
    const float* We2 = (const float*)d_in[4];
    const float* be2 = (const float*)d_in[5];
    const float* Wf1 = (const float*)d_in[6];
    const float* bf1 = (const float*)d_in[7];
    const float* Wf2 = (const float*)d_in[8];
    const float* bf2 = (const float*)d_in[9];
    const float* Wm1 = (const float*)d_in[10];
    const float* bm1 = (const float*)d_in[11];
    const float* Wm2 = (const float*)d_in[12];
    const float* bm2 = (const float*)d_in[13];
    float* out = (float*)d_out;

    // 8 threads per batch element: 65536 threads, 1024 CTAs of 64
    dim3 block(64);
    dim3 grid((B_TOT * 8) / 64);
    latode_kernel<<<grid, block>>>(dt, x, We1, be1, We2, be2,
                                   Wf1, bf1, Wf2, bf2, Wm1, bm1, Wm2, bm2, out);
}